// round 5
// baseline (speedup 1.0000x reference)
#include <cuda_runtime.h>

// LDE_58961311040249 — R5: 512 threads (16 warps) for latency hiding,
// x stored pre-duplicated (u64 (x,x) pairs) serving both GEMMs, norms fused
// into GEMM1, f32x2 throughout.
//   d[b,t,k]  = s[k] * (||x_bt||^2 - 2 x_bt·m_k + ||m_k||^2)
//   w         = softmax_k(d)
//   out[b,k,i]= (sum_t w*x_i)/T - m[i,k]*(sum_t w)/T

#define B_      16
#define T_      2048
#define NIN     128
#define NOUT    64
#define CHUNKS  16
#define TILE_T  (T_ / CHUNKS)   // 128

#define XD_LD   130   // x_dup row stride in u64 (even -> 16B-aligned rows)
#define WS_LD   68    // w row stride (floats)

__device__ float g_partE [B_ * CHUNKS * NIN * NOUT];  // [b][c][i][k], 8 MB
__device__ float g_partWS[B_ * CHUNKS * NOUT];

typedef unsigned long long u64;

__device__ __forceinline__ u64 lds_u64(unsigned off) {
    u64 r; asm volatile("ld.shared.u64 %0, [%1];" : "=l"(r) : "r"(off)); return r;
}
__device__ __forceinline__ void lds_v2u(u64 &p0, u64 &p1, unsigned off) {
    asm volatile("ld.shared.v2.u64 {%0,%1}, [%2];" : "=l"(p0), "=l"(p1) : "r"(off));
}
__device__ __forceinline__ float lds_f(unsigned off) {
    float r; asm volatile("ld.shared.f32 %0, [%1];" : "=f"(r) : "r"(off)); return r;
}
__device__ __forceinline__ void fma2(u64 &d, u64 a, u64 b) {
    asm("fma.rn.f32x2 %0, %1, %2, %0;" : "+l"(d) : "l"(a), "l"(b));
}
__device__ __forceinline__ u64 dup2(float v) {
    u64 d; asm("mov.b64 %0, {%1,%1};" : "=l"(d) : "f"(v)); return d;
}
__device__ __forceinline__ float2 unpack2(u64 v) {
    float2 r; asm("mov.b64 {%0,%1}, %2;" : "=f"(r.x), "=f"(r.y) : "l"(v)); return r;
}

__global__ __launch_bounds__(512, 1) void lde_phase1(
    const float* __restrict__ x,
    const float* __restrict__ s,
    const float* __restrict__ m)
{
    extern __shared__ float smf[];
    u64*   x2  = (u64*)smf;                      // 128*130 u64 (133120 B), (x,x)
    float* m_s = (float*)(x2 + TILE_T * XD_LD);  // 128*64 natural [i][k] (32768 B)
    float* w_s = m_s + NIN * NOUT;               // 128*68 [r][k] (34816 B)
    float* mn  = w_s + TILE_T * WS_LD;           // 64
    float* s_s = mn + NOUT;                      // 64

    const int tid = threadIdx.x;
    const int c   = blockIdx.x;
    const int b   = blockIdx.y;
    const float* xg = x + ((size_t)b * T_ + (size_t)c * TILE_T) * NIN;

    // ---- load M natural [i][k]: dense float4 copy ----
    for (int e = tid; e < (NIN * NOUT) / 4; e += 512) {
        float4 v = reinterpret_cast<const float4*>(m)[e];
        reinterpret_cast<float4*>(m_s)[e] = v;
    }
    // ---- load X tile as duplicated u64 pairs ----
    for (int e = tid; e < TILE_T * (NIN / 4); e += 512) {
        int r = e >> 5, i4 = (e & 31) * 4;
        float4 v = reinterpret_cast<const float4*>(xg + r * NIN)[e & 31];
        u64* dst = x2 + r * XD_LD + i4;
        ulonglong2 p0; p0.x = dup2(v.x); p0.y = dup2(v.y);
        ulonglong2 p1; p1.x = dup2(v.z); p1.y = dup2(v.w);
        *reinterpret_cast<ulonglong2*>(dst)     = p0;
        *reinterpret_cast<ulonglong2*>(dst + 2) = p1;
    }
    if (tid >= 448) s_s[tid - 448] = s[tid - 448];
    __syncthreads();

    const unsigned xb = (unsigned)__cvta_generic_to_shared(x2);
    const unsigned mb = (unsigned)__cvta_generic_to_shared(m_s);
    const unsigned wb = (unsigned)__cvta_generic_to_shared(w_s);

    // ---- mn[k] = ||m_k||^2 (64 threads, lanes consecutive k: conflict-free) ----
    if (tid < NOUT) {
        float a = 0.f;
        #pragma unroll 8
        for (int i = 0; i < NIN; i++) {
            float v = lds_f(mb + (unsigned)(i * NOUT + tid) * 4u);
            a += v * v;
        }
        mn[tid] = a;
    }
    __syncthreads();

    // ======== GEMM1: dot[r][k], tile 2r x 8k, norms fused ========
    const int kb = tid & 7;            // k = 8*kb .. 8*kb+7
    const int rb = tid >> 3;           // 0..63
    const int r0 = rb * 2;
    u64 acc[2][4];                     // [row][kpair]
    u64 nrm[2];
    acc[0][0]=acc[0][1]=acc[0][2]=acc[0][3]=0ull;
    acc[1][0]=acc[1][1]=acc[1][2]=acc[1][3]=0ull;
    nrm[0]=nrm[1]=0ull;

    const unsigned ax0 = xb + (unsigned)(r0 * XD_LD) * 8u;
    const unsigned ax1 = ax0 + (unsigned)XD_LD * 8u;
    const unsigned bx  = mb + (unsigned)(kb * 8) * 4u;

    #pragma unroll 4
    for (int i = 0; i < NIN; i++) {
        u64 a0 = lds_u64(ax0 + (unsigned)i * 8u);
        u64 a1 = lds_u64(ax1 + (unsigned)i * 8u);
        u64 b0, b1, b2, b3;
        lds_v2u(b0, b1, bx + (unsigned)(i * NOUT) * 4u);
        lds_v2u(b2, b3, bx + (unsigned)(i * NOUT) * 4u + 16u);
        fma2(acc[0][0], a0, b0); fma2(acc[0][1], a0, b1);
        fma2(acc[0][2], a0, b2); fma2(acc[0][3], a0, b3);
        fma2(acc[1][0], a1, b0); fma2(acc[1][1], a1, b1);
        fma2(acc[1][2], a1, b2); fma2(acc[1][3], a1, b3);
        fma2(nrm[0], a0, a0);    fma2(nrm[1], a1, a1);
    }

    // ======== d-transform + softmax over k (8-lane xor shuffles) ========
    float mnl[8], ssl[8];
    #pragma unroll
    for (int q = 0; q < 8; q++) { mnl[q] = mn[kb * 8 + q]; ssl[q] = s_s[kb * 8 + q]; }

    #pragma unroll
    for (int u = 0; u < 2; u++) {
        const int r = r0 + u;
        const float xr = unpack2(nrm[u]).x;
        float dv[8];
        #pragma unroll
        for (int j = 0; j < 4; j++) {
            float2 p = unpack2(acc[u][j]);
            dv[2*j]   = ssl[2*j]   * (xr - 2.f * p.x + mnl[2*j]);
            dv[2*j+1] = ssl[2*j+1] * (xr - 2.f * p.y + mnl[2*j+1]);
        }
        float mx = dv[0];
        #pragma unroll
        for (int q = 1; q < 8; q++) mx = fmaxf(mx, dv[q]);
        #pragma unroll
        for (int off = 1; off < 8; off <<= 1)
            mx = fmaxf(mx, __shfl_xor_sync(0xffffffffu, mx, off));

        float ev[8], sum = 0.f;
        #pragma unroll
        for (int q = 0; q < 8; q++) { ev[q] = __expf(dv[q] - mx); sum += ev[q]; }
        #pragma unroll
        for (int off = 1; off < 8; off <<= 1)
            sum += __shfl_xor_sync(0xffffffffu, sum, off);

        const float inv = 1.f / sum;
        float* wr = w_s + r * WS_LD + kb * 8;
        *reinterpret_cast<float4*>(wr) =
            make_float4(ev[0]*inv, ev[1]*inv, ev[2]*inv, ev[3]*inv);
        *reinterpret_cast<float4*>(wr + 4) =
            make_float4(ev[4]*inv, ev[5]*inv, ev[6]*inv, ev[7]*inv);
    }
    __syncthreads();

    // ======== GEMM2: E[i][k] = sum_r w[r][k]*x[r][i], pairs along k ========
    // thread (kb, ib): i in {ib, ib+64}
    const int ib = tid >> 3;           // 0..63
    u64 acc2[2][4];
    acc2[0][0]=acc2[0][1]=acc2[0][2]=acc2[0][3]=0ull;
    acc2[1][0]=acc2[1][1]=acc2[1][2]=acc2[1][3]=0ull;

    const unsigned wx  = wb + (unsigned)(kb * 8) * 4u;
    const unsigned xi0 = xb + (unsigned)ib * 8u;
    const unsigned xi1 = xb + (unsigned)(ib + 64) * 8u;

    #pragma unroll 4
    for (int r = 0; r < TILE_T; r++) {
        u64 w0, w1, w2, w3;
        lds_v2u(w0, w1, wx + (unsigned)(r * WS_LD) * 4u);
        lds_v2u(w2, w3, wx + (unsigned)(r * WS_LD) * 4u + 16u);
        u64 xa = lds_u64(xi0 + (unsigned)(r * XD_LD) * 8u);
        u64 xc = lds_u64(xi1 + (unsigned)(r * XD_LD) * 8u);
        fma2(acc2[0][0], w0, xa); fma2(acc2[0][1], w1, xa);
        fma2(acc2[0][2], w2, xa); fma2(acc2[0][3], w3, xa);
        fma2(acc2[1][0], w0, xc); fma2(acc2[1][1], w1, xc);
        fma2(acc2[1][2], w2, xc); fma2(acc2[1][3], w3, xc);
    }

    float* pe = g_partE + (size_t)(b * CHUNKS + c) * NIN * NOUT;
    #pragma unroll
    for (int v = 0; v < 2; v++) {
        const int i = ib + 64 * v;
        ulonglong2 o0; o0.x = acc2[v][0]; o0.y = acc2[v][1];
        ulonglong2 o1; o1.x = acc2[v][2]; o1.y = acc2[v][3];
        *reinterpret_cast<ulonglong2*>(pe + i * NOUT + kb * 8)     = o0;
        *reinterpret_cast<ulonglong2*>(pe + i * NOUT + kb * 8 + 4) = o1;
    }

    // ---- per-chunk wsum[k] ----
    if (tid < NOUT) {
        float a = 0.f;
        #pragma unroll 8
        for (int r = 0; r < TILE_T; r++) a += w_s[r * WS_LD + tid];
        g_partWS[(b * CHUNKS + c) * NOUT + tid] = a;
    }
}

__global__ __launch_bounds__(256) void lde_phase2(
    const float* __restrict__ m, float* __restrict__ out)
{
    const int g  = blockIdx.x * 256 + threadIdx.x;  // 65536 = B*NIN*32
    const int b  = g >> 12;
    const int i  = (g >> 5) & 127;
    const int k2 = g & 31;                          // pair of k

    float2 se = make_float2(0.f, 0.f);
    float2 sw = make_float2(0.f, 0.f);
    #pragma unroll
    for (int c = 0; c < CHUNKS; c++) {
        const float2 v = *reinterpret_cast<const float2*>(
            g_partE + ((size_t)((b * CHUNKS + c) * NIN + i)) * NOUT + k2 * 2);
        se.x += v.x; se.y += v.y;
        const float2 wv = *reinterpret_cast<const float2*>(
            g_partWS + (b * CHUNKS + c) * NOUT + k2 * 2);
        sw.x += wv.x; sw.y += wv.y;
    }
    const float2 mv = *reinterpret_cast<const float2*>(m + i * NOUT + k2 * 2);
    const float inv_t = 1.f / (float)T_;
    float* ob = out + (size_t)b * NOUT * NIN + i;
    ob[(k2 * 2 + 0) * NIN] = (se.x - mv.x * sw.x) * inv_t;
    ob[(k2 * 2 + 1) * NIN] = (se.y - mv.y * sw.y) * inv_t;
}

extern "C" void kernel_launch(void* const* d_in, const int* in_sizes, int n_in,
                              void* d_out, int out_size)
{
    const float* x = nullptr; const float* s = nullptr; const float* m = nullptr;
    for (int i = 0; i < n_in; i++) {
        if      (in_sizes[i] == B_ * T_ * NIN) x = (const float*)d_in[i];
        else if (in_sizes[i] == NOUT)          s = (const float*)d_in[i];
        else if (in_sizes[i] == NIN * NOUT)    m = (const float*)d_in[i];
    }
    float* out = (float*)d_out;

    const int smem_bytes =
        TILE_T * XD_LD * (int)sizeof(u64)
        + (NIN * NOUT + TILE_T * WS_LD + 2 * NOUT) * (int)sizeof(float); // ~201 KB

    cudaFuncSetAttribute(lde_phase1,
                         cudaFuncAttributeMaxDynamicSharedMemorySize, smem_bytes);

    lde_phase1<<<dim3(CHUNKS, B_), 512, smem_bytes>>>(x, s, m);
    lde_phase2<<<(B_ * NIN * 32) / 256, 256>>>(m, out);
}

// round 6
// speedup vs baseline: 1.5698x; 1.5698x over previous
#include <cuda_runtime.h>

// LDE_58961311040249 — R6: R4 layout + m/w SMEM union -> 2 CTAs/SM, single
// wave. Launch pattern [dummy, p1, p2, dummy] so ncu (-s 5) captures phase1.
//   d[b,t,k]  = s[k] * (||x_bt||^2 - 2 x_bt·m_k + ||m_k||^2)
//   w         = softmax_k(d)
//   out[b,k,i]= (sum_t w*x_i)/T - m[i,k]*(sum_t w)/T

#define B_      16
#define T_      2048
#define NIN     128
#define NOUT    64
#define CHUNKS  16
#define TILE_T  (T_ / CHUNKS)   // 128

#define XS_LD   130   // x row stride (floats)
#define WS_LD   68    // w row stride (floats)

__device__ float g_partE [B_ * CHUNKS * NIN * NOUT];  // [b][c][i][k], 8 MB
__device__ float g_partWS[B_ * CHUNKS * NOUT];

typedef unsigned long long u64;

__device__ __forceinline__ void lds_v2u(u64 &p0, u64 &p1, unsigned off) {
    asm volatile("ld.shared.v2.u64 {%0,%1}, [%2];" : "=l"(p0), "=l"(p1) : "r"(off));
}
__device__ __forceinline__ float2 lds_v2f(unsigned off) {
    float2 r;
    asm volatile("ld.shared.v2.f32 {%0,%1}, [%2];" : "=f"(r.x), "=f"(r.y) : "r"(off));
    return r;
}
__device__ __forceinline__ float lds_f(unsigned off) {
    float r; asm volatile("ld.shared.f32 %0, [%1];" : "=f"(r) : "r"(off)); return r;
}
__device__ __forceinline__ void fma2(u64 &d, u64 a, u64 b) {
    asm("fma.rn.f32x2 %0, %1, %2, %0;" : "+l"(d) : "l"(a), "l"(b));
}
__device__ __forceinline__ u64 dup2(float v) {
    u64 d; asm("mov.b64 %0, {%1,%1};" : "=l"(d) : "f"(v)); return d;
}
__device__ __forceinline__ float2 unpack2(u64 v) {
    float2 r; asm("mov.b64 {%0,%1}, %2;" : "=f"(r.x), "=f"(r.y) : "l"(v)); return r;
}

__global__ void lde_dummy() {}

__global__ __launch_bounds__(256, 2) void lde_phase1(
    const float* __restrict__ x,
    const float* __restrict__ s,
    const float* __restrict__ m)
{
    extern __shared__ float smf[];
    float* x_s = smf;                         // 128*130 = 16640 f
    float* m_s = x_s + TILE_T * XS_LD;        // union: m[i][k] dense (8192 f)
    float* w_s = m_s;                         //        w[r][k] WS_LD  (8704 f)
    float* mn  = m_s + TILE_T * WS_LD;        // 64  (after the 8704-f union)
    float* s_s = mn + NOUT;                   // 64

    const int tid = threadIdx.x;
    const int c   = blockIdx.x;
    const int b   = blockIdx.y;
    const float* xg = x + ((size_t)b * T_ + (size_t)c * TILE_T) * NIN;

    // ---- load M natural [i][k]: dense float4 copy ----
    for (int e = tid; e < (NIN * NOUT) / 4; e += 256) {
        float4 v = reinterpret_cast<const float4*>(m)[e];
        reinterpret_cast<float4*>(m_s)[e] = v;
    }
    // ---- load X tile ----
    for (int e = tid; e < TILE_T * (NIN / 4); e += 256) {
        int r = e >> 5, i4 = (e & 31) * 4;
        float4 v = reinterpret_cast<const float4*>(xg + r * NIN)[e & 31];
        float* dst = x_s + r * XS_LD + i4;
        *reinterpret_cast<float2*>(dst)     = make_float2(v.x, v.y);
        *reinterpret_cast<float2*>(dst + 2) = make_float2(v.z, v.w);
    }
    __syncthreads();

    const unsigned xb = (unsigned)__cvta_generic_to_shared(x_s);
    const unsigned mb = (unsigned)__cvta_generic_to_shared(m_s);
    const unsigned wb = (unsigned)__cvta_generic_to_shared(w_s);

    // ---- mn[k] = ||m_k||^2 ; xn folded below is not needed (recomputed) ----
    if (tid < NOUT) {
        float a = 0.f;
        #pragma unroll 8
        for (int i = 0; i < NIN; i++) {
            float v = lds_f(mb + (unsigned)(i * NOUT + tid) * 4u);
            a += v * v;
        }
        mn[tid] = a;
    } else if (tid >= 192) {
        s_s[tid - 192] = s[tid - 192];
    }
    __syncthreads();

    // ======== GEMM1: dot[r][k], pairs along k. tile 4r x 8k ========
    const int kb = tid & 7;           // k = 8*kb .. 8*kb+7
    const int rb = tid >> 3;          // 0..31
    const int r0 = rb * 4;
    u64 acc[4][4];                    // [u=row][j=kpair]
    u64 nrm[4];
    #pragma unroll
    for (int u = 0; u < 4; u++) {
        nrm[u] = 0ull;
        #pragma unroll
        for (int j = 0; j < 4; j++) acc[u][j] = 0ull;
    }

    const unsigned ax = xb + (unsigned)(r0 * XS_LD) * 4u;
    const unsigned bx = mb + (unsigned)(kb * 8) * 4u;

    #pragma unroll 2
    for (int i = 0; i < NIN; i += 2) {
        float2 av[4];
        #pragma unroll
        for (int u = 0; u < 4; u++)
            av[u] = lds_v2f(ax + (unsigned)(u * XS_LD + i) * 4u);
        u64 bp[4], cp[4];
        lds_v2u(bp[0], bp[1], bx + (unsigned)(i * NOUT) * 4u);
        lds_v2u(bp[2], bp[3], bx + (unsigned)(i * NOUT) * 4u + 16u);
        lds_v2u(cp[0], cp[1], bx + (unsigned)((i + 1) * NOUT) * 4u);
        lds_v2u(cp[2], cp[3], bx + (unsigned)((i + 1) * NOUT) * 4u + 16u);
        u64 a0[4], a1[4];
        #pragma unroll
        for (int u = 0; u < 4; u++) { a0[u] = dup2(av[u].x); a1[u] = dup2(av[u].y); }
        #pragma unroll
        for (int u = 0; u < 4; u++) {
            #pragma unroll
            for (int j = 0; j < 4; j++) {
                fma2(acc[u][j], a0[u], bp[j]);
                fma2(acc[u][j], a1[u], cp[j]);
            }
            fma2(nrm[u], a0[u], a0[u]);
            fma2(nrm[u], a1[u], a1[u]);
        }
    }

    // All GEMM1 reads of m_s must complete before w_s (alias) is written.
    __syncthreads();

    // ======== d-transform + softmax over k (8-lane xor shuffles) ========
    float mnl[8], ssl[8];
    #pragma unroll
    for (int q = 0; q < 8; q++) { mnl[q] = mn[kb * 8 + q]; ssl[q] = s_s[kb * 8 + q]; }

    #pragma unroll
    for (int u = 0; u < 4; u++) {
        const int r = r0 + u;
        float2 np = unpack2(nrm[u]);
        const float xr = np.x;        // both halves equal (dup operands)
        float dv[8];
        #pragma unroll
        for (int j = 0; j < 4; j++) {
            float2 p = unpack2(acc[u][j]);
            dv[2*j]   = ssl[2*j]   * (xr - 2.f * p.x + mnl[2*j]);
            dv[2*j+1] = ssl[2*j+1] * (xr - 2.f * p.y + mnl[2*j+1]);
        }
        float mx = dv[0];
        #pragma unroll
        for (int q = 1; q < 8; q++) mx = fmaxf(mx, dv[q]);
        #pragma unroll
        for (int off = 1; off < 8; off <<= 1)
            mx = fmaxf(mx, __shfl_xor_sync(0xffffffffu, mx, off));

        float ev[8], sum = 0.f;
        #pragma unroll
        for (int q = 0; q < 8; q++) { ev[q] = __expf(dv[q] - mx); sum += ev[q]; }
        #pragma unroll
        for (int off = 1; off < 8; off <<= 1)
            sum += __shfl_xor_sync(0xffffffffu, sum, off);

        const float inv = 1.f / sum;
        float* wr = w_s + r * WS_LD + kb * 8;
        *reinterpret_cast<float4*>(wr) =
            make_float4(ev[0]*inv, ev[1]*inv, ev[2]*inv, ev[3]*inv);
        *reinterpret_cast<float4*>(wr + 4) =
            make_float4(ev[4]*inv, ev[5]*inv, ev[6]*inv, ev[7]*inv);
    }
    __syncthreads();

    // ======== GEMM2: E[i][k] = sum_r w[r][k]*x[r][i], pairs along k ========
    const int ib = tid >> 3;          // i in {ib, ib+32, ib+64, ib+96}
    u64 acc2[4][4];                   // [j=kpair][v=i]
    #pragma unroll
    for (int j = 0; j < 4; j++)
        #pragma unroll
        for (int v = 0; v < 4; v++) acc2[j][v] = 0ull;

    const unsigned wx = wb + (unsigned)(kb * 8) * 4u;

    #pragma unroll 4
    for (int r = 0; r < TILE_T; r++) {
        u64 wp[4];
        lds_v2u(wp[0], wp[1], wx + (unsigned)(r * WS_LD) * 4u);
        lds_v2u(wp[2], wp[3], wx + (unsigned)(r * WS_LD) * 4u + 16u);
        u64 xd[4];
        #pragma unroll
        for (int v = 0; v < 4; v++)
            xd[v] = dup2(lds_f(xb + (unsigned)(r * XS_LD + ib + 32 * v) * 4u));
        #pragma unroll
        for (int j = 0; j < 4; j++)
            #pragma unroll
            for (int v = 0; v < 4; v++)
                fma2(acc2[j][v], wp[j], xd[v]);
    }

    float* pe = g_partE + (size_t)(b * CHUNKS + c) * NIN * NOUT;
    #pragma unroll
    for (int v = 0; v < 4; v++) {
        const int i = ib + 32 * v;
        #pragma unroll
        for (int j = 0; j < 4; j++)
            *reinterpret_cast<u64*>(pe + i * NOUT + kb * 8 + 2 * j) = acc2[j][v];
    }

    // ---- per-chunk wsum[k] ----
    if (tid < NOUT) {
        float a = 0.f;
        #pragma unroll 8
        for (int r = 0; r < TILE_T; r++) a += w_s[r * WS_LD + tid];
        g_partWS[(b * CHUNKS + c) * NOUT + tid] = a;
    }
}

__global__ __launch_bounds__(256) void lde_phase2(
    const float* __restrict__ m, float* __restrict__ out)
{
    const int g  = blockIdx.x * 256 + threadIdx.x;  // 65536 = B*NIN*32
    const int b  = g >> 12;
    const int i  = (g >> 5) & 127;
    const int k2 = g & 31;                          // pair of k

    float2 se = make_float2(0.f, 0.f);
    float2 sw = make_float2(0.f, 0.f);
    #pragma unroll
    for (int c = 0; c < CHUNKS; c++) {
        const float2 v = *reinterpret_cast<const float2*>(
            g_partE + ((size_t)((b * CHUNKS + c) * NIN + i)) * NOUT + k2 * 2);
        se.x += v.x; se.y += v.y;
        const float2 wv = *reinterpret_cast<const float2*>(
            g_partWS + (b * CHUNKS + c) * NOUT + k2 * 2);
        sw.x += wv.x; sw.y += wv.y;
    }
    const float2 mv = *reinterpret_cast<const float2*>(m + i * NOUT + k2 * 2);
    const float inv_t = 1.f / (float)T_;
    float* ob = out + (size_t)b * NOUT * NIN + i;
    ob[(k2 * 2 + 0) * NIN] = (se.x - mv.x * sw.x) * inv_t;
    ob[(k2 * 2 + 1) * NIN] = (se.y - mv.y * sw.y) * inv_t;
}

extern "C" void kernel_launch(void* const* d_in, const int* in_sizes, int n_in,
                              void* d_out, int out_size)
{
    const float* x = nullptr; const float* s = nullptr; const float* m = nullptr;
    for (int i = 0; i < n_in; i++) {
        if      (in_sizes[i] == B_ * T_ * NIN) x = (const float*)d_in[i];
        else if (in_sizes[i] == NOUT)          s = (const float*)d_in[i];
        else if (in_sizes[i] == NIN * NOUT)    m = (const float*)d_in[i];
    }
    float* out = (float*)d_out;

    const int smem_bytes =
        (TILE_T * XS_LD + TILE_T * WS_LD + 2 * NOUT) * (int)sizeof(float); // ~102 KB

    cudaFuncSetAttribute(lde_phase1,
                         cudaFuncAttributeMaxDynamicSharedMemorySize, smem_bytes);

    // 4 launches/call so ncu (-s 5 -c 1) lands on phase1 (index 5 mod 4 == 1).
    lde_dummy<<<1, 32>>>();
    lde_phase1<<<dim3(CHUNKS, B_), 256, smem_bytes>>>(x, s, m);
    lde_phase2<<<(B_ * NIN * 32) / 256, 256>>>(m, out);
    lde_dummy<<<1, 32>>>();
}

// round 7
// speedup vs baseline: 1.6073x; 1.0238x over previous
#include <cuda_runtime.h>

// LDE_58961311040249 — R7: identical phase1/phase2 to R6 (best: 57.7us).
// Launch pattern [p1, p2, dummy]: with the observed +2 launch offset in the
// profiled stream, ncu -s 5 -c 1 lands on (5-2) mod 3 == 0 -> phase1.
//   d[b,t,k]  = s[k] * (||x_bt||^2 - 2 x_bt·m_k + ||m_k||^2)
//   w         = softmax_k(d)
//   out[b,k,i]= (sum_t w*x_i)/T - m[i,k]*(sum_t w)/T

#define B_      16
#define T_      2048
#define NIN     128
#define NOUT    64
#define CHUNKS  16
#define TILE_T  (T_ / CHUNKS)   // 128

#define XS_LD   130   // x row stride (floats)
#define WS_LD   68    // w row stride (floats)

__device__ float g_partE [B_ * CHUNKS * NIN * NOUT];  // [b][c][i][k], 8 MB
__device__ float g_partWS[B_ * CHUNKS * NOUT];

typedef unsigned long long u64;

__device__ __forceinline__ void lds_v2u(u64 &p0, u64 &p1, unsigned off) {
    asm volatile("ld.shared.v2.u64 {%0,%1}, [%2];" : "=l"(p0), "=l"(p1) : "r"(off));
}
__device__ __forceinline__ float2 lds_v2f(unsigned off) {
    float2 r;
    asm volatile("ld.shared.v2.f32 {%0,%1}, [%2];" : "=f"(r.x), "=f"(r.y) : "r"(off));
    return r;
}
__device__ __forceinline__ float lds_f(unsigned off) {
    float r; asm volatile("ld.shared.f32 %0, [%1];" : "=f"(r) : "r"(off)); return r;
}
__device__ __forceinline__ void fma2(u64 &d, u64 a, u64 b) {
    asm("fma.rn.f32x2 %0, %1, %2, %0;" : "+l"(d) : "l"(a), "l"(b));
}
__device__ __forceinline__ u64 dup2(float v) {
    u64 d; asm("mov.b64 %0, {%1,%1};" : "=l"(d) : "f"(v)); return d;
}
__device__ __forceinline__ float2 unpack2(u64 v) {
    float2 r; asm("mov.b64 {%0,%1}, %2;" : "=f"(r.x), "=f"(r.y) : "l"(v)); return r;
}

__global__ void lde_dummy() {}

__global__ __launch_bounds__(256, 2) void lde_phase1(
    const float* __restrict__ x,
    const float* __restrict__ s,
    const float* __restrict__ m)
{
    extern __shared__ float smf[];
    float* x_s = smf;                         // 128*130 = 16640 f
    float* m_s = x_s + TILE_T * XS_LD;        // union: m[i][k] dense (8192 f)
    float* w_s = m_s;                         //        w[r][k] WS_LD  (8704 f)
    float* mn  = m_s + TILE_T * WS_LD;        // 64  (after the 8704-f union)
    float* s_s = mn + NOUT;                   // 64

    const int tid = threadIdx.x;
    const int c   = blockIdx.x;
    const int b   = blockIdx.y;
    const float* xg = x + ((size_t)b * T_ + (size_t)c * TILE_T) * NIN;

    // ---- load M natural [i][k]: dense float4 copy ----
    for (int e = tid; e < (NIN * NOUT) / 4; e += 256) {
        float4 v = reinterpret_cast<const float4*>(m)[e];
        reinterpret_cast<float4*>(m_s)[e] = v;
    }
    // ---- load X tile ----
    for (int e = tid; e < TILE_T * (NIN / 4); e += 256) {
        int r = e >> 5, i4 = (e & 31) * 4;
        float4 v = reinterpret_cast<const float4*>(xg + r * NIN)[e & 31];
        float* dst = x_s + r * XS_LD + i4;
        *reinterpret_cast<float2*>(dst)     = make_float2(v.x, v.y);
        *reinterpret_cast<float2*>(dst + 2) = make_float2(v.z, v.w);
    }
    __syncthreads();

    const unsigned xb = (unsigned)__cvta_generic_to_shared(x_s);
    const unsigned mb = (unsigned)__cvta_generic_to_shared(m_s);
    const unsigned wb = (unsigned)__cvta_generic_to_shared(w_s);

    // ---- mn[k] = ||m_k||^2 ----
    if (tid < NOUT) {
        float a = 0.f;
        #pragma unroll 8
        for (int i = 0; i < NIN; i++) {
            float v = lds_f(mb + (unsigned)(i * NOUT + tid) * 4u);
            a += v * v;
        }
        mn[tid] = a;
    } else if (tid >= 192) {
        s_s[tid - 192] = s[tid - 192];
    }
    __syncthreads();

    // ======== GEMM1: dot[r][k], pairs along k. tile 4r x 8k ========
    const int kb = tid & 7;           // k = 8*kb .. 8*kb+7
    const int rb = tid >> 3;          // 0..31
    const int r0 = rb * 4;
    u64 acc[4][4];                    // [u=row][j=kpair]
    u64 nrm[4];
    #pragma unroll
    for (int u = 0; u < 4; u++) {
        nrm[u] = 0ull;
        #pragma unroll
        for (int j = 0; j < 4; j++) acc[u][j] = 0ull;
    }

    const unsigned ax = xb + (unsigned)(r0 * XS_LD) * 4u;
    const unsigned bx = mb + (unsigned)(kb * 8) * 4u;

    #pragma unroll 2
    for (int i = 0; i < NIN; i += 2) {
        float2 av[4];
        #pragma unroll
        for (int u = 0; u < 4; u++)
            av[u] = lds_v2f(ax + (unsigned)(u * XS_LD + i) * 4u);
        u64 bp[4], cp[4];
        lds_v2u(bp[0], bp[1], bx + (unsigned)(i * NOUT) * 4u);
        lds_v2u(bp[2], bp[3], bx + (unsigned)(i * NOUT) * 4u + 16u);
        lds_v2u(cp[0], cp[1], bx + (unsigned)((i + 1) * NOUT) * 4u);
        lds_v2u(cp[2], cp[3], bx + (unsigned)((i + 1) * NOUT) * 4u + 16u);
        u64 a0[4], a1[4];
        #pragma unroll
        for (int u = 0; u < 4; u++) { a0[u] = dup2(av[u].x); a1[u] = dup2(av[u].y); }
        #pragma unroll
        for (int u = 0; u < 4; u++) {
            #pragma unroll
            for (int j = 0; j < 4; j++) {
                fma2(acc[u][j], a0[u], bp[j]);
                fma2(acc[u][j], a1[u], cp[j]);
            }
            fma2(nrm[u], a0[u], a0[u]);
            fma2(nrm[u], a1[u], a1[u]);
        }
    }

    // All GEMM1 reads of m_s must complete before w_s (alias) is written.
    __syncthreads();

    // ======== d-transform + softmax over k (8-lane xor shuffles) ========
    float mnl[8], ssl[8];
    #pragma unroll
    for (int q = 0; q < 8; q++) { mnl[q] = mn[kb * 8 + q]; ssl[q] = s_s[kb * 8 + q]; }

    #pragma unroll
    for (int u = 0; u < 4; u++) {
        const int r = r0 + u;
        float2 np = unpack2(nrm[u]);
        const float xr = np.x;
        float dv[8];
        #pragma unroll
        for (int j = 0; j < 4; j++) {
            float2 p = unpack2(acc[u][j]);
            dv[2*j]   = ssl[2*j]   * (xr - 2.f * p.x + mnl[2*j]);
            dv[2*j+1] = ssl[2*j+1] * (xr - 2.f * p.y + mnl[2*j+1]);
        }
        float mx = dv[0];
        #pragma unroll
        for (int q = 1; q < 8; q++) mx = fmaxf(mx, dv[q]);
        #pragma unroll
        for (int off = 1; off < 8; off <<= 1)
            mx = fmaxf(mx, __shfl_xor_sync(0xffffffffu, mx, off));

        float ev[8], sum = 0.f;
        #pragma unroll
        for (int q = 0; q < 8; q++) { ev[q] = __expf(dv[q] - mx); sum += ev[q]; }
        #pragma unroll
        for (int off = 1; off < 8; off <<= 1)
            sum += __shfl_xor_sync(0xffffffffu, sum, off);

        const float inv = 1.f / sum;
        float* wr = w_s + r * WS_LD + kb * 8;
        *reinterpret_cast<float4*>(wr) =
            make_float4(ev[0]*inv, ev[1]*inv, ev[2]*inv, ev[3]*inv);
        *reinterpret_cast<float4*>(wr + 4) =
            make_float4(ev[4]*inv, ev[5]*inv, ev[6]*inv, ev[7]*inv);
    }
    __syncthreads();

    // ======== GEMM2: E[i][k] = sum_r w[r][k]*x[r][i], pairs along k ========
    const int ib = tid >> 3;          // i in {ib, ib+32, ib+64, ib+96}
    u64 acc2[4][4];                   // [j=kpair][v=i]
    #pragma unroll
    for (int j = 0; j < 4; j++)
        #pragma unroll
        for (int v = 0; v < 4; v++) acc2[j][v] = 0ull;

    const unsigned wx = wb + (unsigned)(kb * 8) * 4u;

    #pragma unroll 4
    for (int r = 0; r < TILE_T; r++) {
        u64 wp[4];
        lds_v2u(wp[0], wp[1], wx + (unsigned)(r * WS_LD) * 4u);
        lds_v2u(wp[2], wp[3], wx + (unsigned)(r * WS_LD) * 4u + 16u);
        u64 xd[4];
        #pragma unroll
        for (int v = 0; v < 4; v++)
            xd[v] = dup2(lds_f(xb + (unsigned)(r * XS_LD + ib + 32 * v) * 4u));
        #pragma unroll
        for (int j = 0; j < 4; j++)
            #pragma unroll
            for (int v = 0; v < 4; v++)
                fma2(acc2[j][v], wp[j], xd[v]);
    }

    float* pe = g_partE + (size_t)(b * CHUNKS + c) * NIN * NOUT;
    #pragma unroll
    for (int v = 0; v < 4; v++) {
        const int i = ib + 32 * v;
        #pragma unroll
        for (int j = 0; j < 4; j++)
            *reinterpret_cast<u64*>(pe + i * NOUT + kb * 8 + 2 * j) = acc2[j][v];
    }

    // ---- per-chunk wsum[k] ----
    if (tid < NOUT) {
        float a = 0.f;
        #pragma unroll 8
        for (int r = 0; r < TILE_T; r++) a += w_s[r * WS_LD + tid];
        g_partWS[(b * CHUNKS + c) * NOUT + tid] = a;
    }
}

__global__ __launch_bounds__(256) void lde_phase2(
    const float* __restrict__ m, float* __restrict__ out)
{
    const int g  = blockIdx.x * 256 + threadIdx.x;  // 65536 = B*NIN*32
    const int b  = g >> 12;
    const int i  = (g >> 5) & 127;
    const int k2 = g & 31;                          // pair of k

    float2 se = make_float2(0.f, 0.f);
    float2 sw = make_float2(0.f, 0.f);
    #pragma unroll
    for (int c = 0; c < CHUNKS; c++) {
        const float2 v = *reinterpret_cast<const float2*>(
            g_partE + ((size_t)((b * CHUNKS + c) * NIN + i)) * NOUT + k2 * 2);
        se.x += v.x; se.y += v.y;
        const float2 wv = *reinterpret_cast<const float2*>(
            g_partWS + (b * CHUNKS + c) * NOUT + k2 * 2);
        sw.x += wv.x; sw.y += wv.y;
    }
    const float2 mv = *reinterpret_cast<const float2*>(m + i * NOUT + k2 * 2);
    const float inv_t = 1.f / (float)T_;
    float* ob = out + (size_t)b * NOUT * NIN + i;
    ob[(k2 * 2 + 0) * NIN] = (se.x - mv.x * sw.x) * inv_t;
    ob[(k2 * 2 + 1) * NIN] = (se.y - mv.y * sw.y) * inv_t;
}

extern "C" void kernel_launch(void* const* d_in, const int* in_sizes, int n_in,
                              void* d_out, int out_size)
{
    const float* x = nullptr; const float* s = nullptr; const float* m = nullptr;
    for (int i = 0; i < n_in; i++) {
        if      (in_sizes[i] == B_ * T_ * NIN) x = (const float*)d_in[i];
        else if (in_sizes[i] == NOUT)          s = (const float*)d_in[i];
        else if (in_sizes[i] == NIN * NOUT)    m = (const float*)d_in[i];
    }
    float* out = (float*)d_out;

    const int smem_bytes =
        (TILE_T * XS_LD + TILE_T * WS_LD + 2 * NOUT) * (int)sizeof(float); // ~102 KB

    cudaFuncSetAttribute(lde_phase1,
                         cudaFuncAttributeMaxDynamicSharedMemorySize, smem_bytes);

    // 3 launches/call: with the +2 stream offset, ncu -s 5 captures phase1.
    lde_phase1<<<dim3(CHUNKS, B_), 256, smem_bytes>>>(x, s, m);
    lde_phase2<<<(B_ * NIN * 32) / 256, 256>>>(m, out);
    lde_dummy<<<1, 32>>>();
}

// round 8
// speedup vs baseline: 2.0717x; 1.2890x over previous
#include <cuda_runtime.h>

// LDE_58961311040249 — R8: phase1 with 128 fat threads (8x8 per-thread tiles)
// to halve LDS-wavefront demand (profiled binder: l1tex 61.7%).
//   d[b,t,k]  = s[k] * (||x_bt||^2 - 2 x_bt·m_k + ||m_k||^2)
//   w         = softmax_k(d)
//   out[b,k,i]= (sum_t w*x_i)/T - m[i,k]*(sum_t w)/T

#define B_      16
#define T_      2048
#define NIN     128
#define NOUT    64
#define CHUNKS  16
#define TILE_T  (T_ / CHUNKS)   // 128

#define XS_LD   130   // x row stride (floats)
#define WS_LD   68    // w row stride (floats)

__device__ float g_partE [B_ * CHUNKS * NIN * NOUT];  // [b][c][i][k], 8 MB
__device__ float g_partWS[B_ * CHUNKS * NOUT];

typedef unsigned long long u64;

__device__ __forceinline__ void lds_v2u(u64 &p0, u64 &p1, unsigned off) {
    asm volatile("ld.shared.v2.u64 {%0,%1}, [%2];" : "=l"(p0), "=l"(p1) : "r"(off));
}
__device__ __forceinline__ float2 lds_v2f(unsigned off) {
    float2 r;
    asm volatile("ld.shared.v2.f32 {%0,%1}, [%2];" : "=f"(r.x), "=f"(r.y) : "r"(off));
    return r;
}
__device__ __forceinline__ float lds_f(unsigned off) {
    float r; asm volatile("ld.shared.f32 %0, [%1];" : "=f"(r) : "r"(off)); return r;
}
__device__ __forceinline__ void fma2(u64 &d, u64 a, u64 b) {
    asm("fma.rn.f32x2 %0, %1, %2, %0;" : "+l"(d) : "l"(a), "l"(b));
}
__device__ __forceinline__ u64 dup2(float v) {
    u64 d; asm("mov.b64 %0, {%1,%1};" : "=l"(d) : "f"(v)); return d;
}
__device__ __forceinline__ float2 unpack2(u64 v) {
    float2 r; asm("mov.b64 {%0,%1}, %2;" : "=f"(r.x), "=f"(r.y) : "l"(v)); return r;
}

__global__ void lde_dummy() {}

__global__ __launch_bounds__(128, 2) void lde_phase1(
    const float* __restrict__ x,
    const float* __restrict__ s,
    const float* __restrict__ m)
{
    extern __shared__ float smf[];
    float* x_s = smf;                         // 128*130 f (66560 B)
    float* m_s = x_s + TILE_T * XS_LD;        // union: m[i][k] dense (8192 f)
    float* w_s = m_s;                         //        w[r][k] WS_LD  (8704 f)
    float* xn  = m_s + TILE_T * WS_LD;        // 128
    float* mn  = xn + TILE_T;                 // 64
    float* s_s = mn + NOUT;                   // 64

    const int tid = threadIdx.x;
    const int c   = blockIdx.x;
    const int b   = blockIdx.y;
    const float* xg = x + ((size_t)b * T_ + (size_t)c * TILE_T) * NIN;

    // ---- load M natural [i][k]: dense float4 copy ----
    for (int e = tid; e < (NIN * NOUT) / 4; e += 128) {
        float4 v = reinterpret_cast<const float4*>(m)[e];
        reinterpret_cast<float4*>(m_s)[e] = v;
    }
    // ---- load X tile ----
    for (int e = tid; e < TILE_T * (NIN / 4); e += 128) {
        int r = e >> 5, i4 = (e & 31) * 4;
        float4 v = reinterpret_cast<const float4*>(xg + r * NIN)[e & 31];
        float* dst = x_s + r * XS_LD + i4;
        *reinterpret_cast<float2*>(dst)     = make_float2(v.x, v.y);
        *reinterpret_cast<float2*>(dst + 2) = make_float2(v.z, v.w);
    }
    __syncthreads();

    const unsigned xb = (unsigned)__cvta_generic_to_shared(x_s);
    const unsigned mb = (unsigned)__cvta_generic_to_shared(m_s);
    const unsigned wb = (unsigned)__cvta_generic_to_shared(w_s);

    // ---- xn[r] = ||x_r||^2 (one row per thread, 2-way conflicts max) ----
    {
        const unsigned base = xb + (unsigned)(tid * XS_LD) * 4u;
        float a = 0.f;
        #pragma unroll 8
        for (int i = 0; i < NIN; i += 2) {
            float2 v = lds_v2f(base + (unsigned)i * 4u);
            a += v.x * v.x + v.y * v.y;
        }
        xn[tid] = a;
    }
    // ---- mn[k] = ||m_k||^2 ; s_s in parallel ----
    if (tid < NOUT) {
        float a = 0.f;
        #pragma unroll 8
        for (int i = 0; i < NIN; i++) {
            float v = lds_f(mb + (unsigned)(i * NOUT + tid) * 4u);
            a += v * v;
        }
        mn[tid] = a;
    } else {
        s_s[tid - 64] = s[tid - 64];
    }
    __syncthreads();

    // ======== GEMM1: dot[r][k], tile 8r x 8k per thread ========
    const int kb = tid & 7;           // k = 8*kb .. 8*kb+7
    const int rb = tid >> 3;          // 0..15
    const int r0 = rb * 8;
    u64 acc[8][4];                    // [u=row][j=kpair]
    #pragma unroll
    for (int u = 0; u < 8; u++)
        #pragma unroll
        for (int j = 0; j < 4; j++) acc[u][j] = 0ull;

    const unsigned ax = xb + (unsigned)(r0 * XS_LD) * 4u;
    const unsigned bx = mb + (unsigned)(kb * 8) * 4u;

    #pragma unroll 2
    for (int i = 0; i < NIN; i += 2) {
        float2 av[8];
        #pragma unroll
        for (int u = 0; u < 8; u++)
            av[u] = lds_v2f(ax + (unsigned)(u * XS_LD + i) * 4u);
        u64 bp[4], cp[4];
        lds_v2u(bp[0], bp[1], bx + (unsigned)(i * NOUT) * 4u);
        lds_v2u(bp[2], bp[3], bx + (unsigned)(i * NOUT) * 4u + 16u);
        lds_v2u(cp[0], cp[1], bx + (unsigned)((i + 1) * NOUT) * 4u);
        lds_v2u(cp[2], cp[3], bx + (unsigned)((i + 1) * NOUT) * 4u + 16u);
        #pragma unroll
        for (int u = 0; u < 8; u++) {
            u64 a0 = dup2(av[u].x), a1 = dup2(av[u].y);
            #pragma unroll
            for (int j = 0; j < 4; j++) {
                fma2(acc[u][j], a0, bp[j]);
                fma2(acc[u][j], a1, cp[j]);
            }
        }
    }

    // All GEMM1 reads of m_s must complete before w_s (alias) is written.
    __syncthreads();

    // ======== d-transform + softmax over k (8-lane xor shuffles) ========
    float mnl[8], ssl[8];
    #pragma unroll
    for (int q = 0; q < 8; q++) { mnl[q] = mn[kb * 8 + q]; ssl[q] = s_s[kb * 8 + q]; }

    #pragma unroll
    for (int u = 0; u < 8; u++) {
        const int r = r0 + u;
        const float xr = xn[r];
        float dv[8];
        #pragma unroll
        for (int j = 0; j < 4; j++) {
            float2 p = unpack2(acc[u][j]);
            dv[2*j]   = ssl[2*j]   * (xr - 2.f * p.x + mnl[2*j]);
            dv[2*j+1] = ssl[2*j+1] * (xr - 2.f * p.y + mnl[2*j+1]);
        }
        float mx = dv[0];
        #pragma unroll
        for (int q = 1; q < 8; q++) mx = fmaxf(mx, dv[q]);
        #pragma unroll
        for (int off = 1; off < 8; off <<= 1)
            mx = fmaxf(mx, __shfl_xor_sync(0xffffffffu, mx, off));

        float ev[8], sum = 0.f;
        #pragma unroll
        for (int q = 0; q < 8; q++) { ev[q] = __expf(dv[q] - mx); sum += ev[q]; }
        #pragma unroll
        for (int off = 1; off < 8; off <<= 1)
            sum += __shfl_xor_sync(0xffffffffu, sum, off);

        const float inv = 1.f / sum;
        float* wr = w_s + r * WS_LD + kb * 8;
        *reinterpret_cast<float4*>(wr) =
            make_float4(ev[0]*inv, ev[1]*inv, ev[2]*inv, ev[3]*inv);
        *reinterpret_cast<float4*>(wr + 4) =
            make_float4(ev[4]*inv, ev[5]*inv, ev[6]*inv, ev[7]*inv);
    }
    __syncthreads();

    // ======== GEMM2: E[i][k] = sum_r w[r][k]*x[r][i], tile 8k x 8i ========
    const int ib = tid >> 3;          // i = ib*8 .. ib*8+7
    const int i0 = ib * 8;
    u64 acc2[4][8];                   // [j=kpair][v=i]
    #pragma unroll
    for (int j = 0; j < 4; j++)
        #pragma unroll
        for (int v = 0; v < 8; v++) acc2[j][v] = 0ull;

    const unsigned wx = wb + (unsigned)(kb * 8) * 4u;
    const unsigned xi = xb + (unsigned)i0 * 4u;

    #pragma unroll 4
    for (int r = 0; r < TILE_T; r++) {
        u64 wp[4];
        lds_v2u(wp[0], wp[1], wx + (unsigned)(r * WS_LD) * 4u);
        lds_v2u(wp[2], wp[3], wx + (unsigned)(r * WS_LD) * 4u + 16u);
        float2 xv[4];
        #pragma unroll
        for (int j = 0; j < 4; j++)
            xv[j] = lds_v2f(xi + (unsigned)(r * XS_LD + 2 * j) * 4u);
        #pragma unroll
        for (int j2 = 0; j2 < 4; j2++) {
            u64 xd0 = dup2(xv[j2].x), xd1 = dup2(xv[j2].y);
            #pragma unroll
            for (int j = 0; j < 4; j++) {
                fma2(acc2[j][2*j2],   wp[j], xd0);
                fma2(acc2[j][2*j2+1], wp[j], xd1);
            }
        }
    }

    float* pe = g_partE + (size_t)(b * CHUNKS + c) * NIN * NOUT;
    #pragma unroll
    for (int v = 0; v < 8; v++) {
        const int i = i0 + v;
        ulonglong2 o0; o0.x = acc2[0][v]; o0.y = acc2[1][v];
        ulonglong2 o1; o1.x = acc2[2][v]; o1.y = acc2[3][v];
        *reinterpret_cast<ulonglong2*>(pe + i * NOUT + kb * 8)     = o0;
        *reinterpret_cast<ulonglong2*>(pe + i * NOUT + kb * 8 + 4) = o1;
    }

    // ---- per-chunk wsum[k] ----
    if (tid < NOUT) {
        float a = 0.f;
        #pragma unroll 8
        for (int r = 0; r < TILE_T; r++) a += w_s[r * WS_LD + tid];
        g_partWS[(b * CHUNKS + c) * NOUT + tid] = a;
    }
}

__global__ __launch_bounds__(256) void lde_phase2(
    const float* __restrict__ m, float* __restrict__ out)
{
    const int g  = blockIdx.x * 256 + threadIdx.x;  // 65536 = B*NIN*32
    const int b  = g >> 12;
    const int i  = (g >> 5) & 127;
    const int k2 = g & 31;                          // pair of k

    float2 se = make_float2(0.f, 0.f);
    float2 sw = make_float2(0.f, 0.f);
    #pragma unroll
    for (int c = 0; c < CHUNKS; c++) {
        const float2 v = *reinterpret_cast<const float2*>(
            g_partE + ((size_t)((b * CHUNKS + c) * NIN + i)) * NOUT + k2 * 2);
        se.x += v.x; se.y += v.y;
        const float2 wv = *reinterpret_cast<const float2*>(
            g_partWS + (b * CHUNKS + c) * NOUT + k2 * 2);
        sw.x += wv.x; sw.y += wv.y;
    }
    const float2 mv = *reinterpret_cast<const float2*>(m + i * NOUT + k2 * 2);
    const float inv_t = 1.f / (float)T_;
    float* ob = out + (size_t)b * NOUT * NIN + i;
    ob[(k2 * 2 + 0) * NIN] = (se.x - mv.x * sw.x) * inv_t;
    ob[(k2 * 2 + 1) * NIN] = (se.y - mv.y * sw.y) * inv_t;
}

extern "C" void kernel_launch(void* const* d_in, const int* in_sizes, int n_in,
                              void* d_out, int out_size)
{
    const float* x = nullptr; const float* s = nullptr; const float* m = nullptr;
    for (int i = 0; i < n_in; i++) {
        if      (in_sizes[i] == B_ * T_ * NIN) x = (const float*)d_in[i];
        else if (in_sizes[i] == NOUT)          s = (const float*)d_in[i];
        else if (in_sizes[i] == NIN * NOUT)    m = (const float*)d_in[i];
    }
    float* out = (float*)d_out;

    const int smem_bytes =
        (TILE_T * XS_LD + TILE_T * WS_LD + TILE_T + 2 * NOUT)
        * (int)sizeof(float);   // ~102 KB

    cudaFuncSetAttribute(lde_phase1,
                         cudaFuncAttributeMaxDynamicSharedMemorySize, smem_bytes);

    // 3 launches/call: with the +2 stream offset, ncu -s 5 captures phase1.
    lde_phase1<<<dim3(CHUNKS, B_), 128, smem_bytes>>>(x, s, m);
    lde_phase2<<<(B_ * NIN * 32) / 256, 256>>>(m, out);
    lde_dummy<<<1, 32>>>();
}

// round 9
// speedup vs baseline: 2.1718x; 1.0483x over previous
#include <cuda_runtime.h>

// LDE_58961311040249 — R9: 256 thin threads (8rx4k / 4kx8i tiles), 2 CTAs/SM,
// 16 warps/SM to cover LDS latency (R8 profile: issue 30.8%, no pipe saturated).
//   d[b,t,k]  = s[k] * (||x_bt||^2 - 2 x_bt·m_k + ||m_k||^2)
//   w         = softmax_k(d)
//   out[b,k,i]= (sum_t w*x_i)/T - m[i,k]*(sum_t w)/T

#define B_      16
#define T_      2048
#define NIN     128
#define NOUT    64
#define CHUNKS  16
#define TILE_T  (T_ / CHUNKS)   // 128

#define XS_LD   130   // x row stride (floats)
#define WS_LD   68    // w row stride (floats)

__device__ float g_partE [B_ * CHUNKS * NIN * NOUT];  // [b][c][i][k], 8 MB
__device__ float g_partWS[B_ * CHUNKS * NOUT];

typedef unsigned long long u64;

__device__ __forceinline__ void lds_v2u(u64 &p0, u64 &p1, unsigned off) {
    asm volatile("ld.shared.v2.u64 {%0,%1}, [%2];" : "=l"(p0), "=l"(p1) : "r"(off));
}
__device__ __forceinline__ float2 lds_v2f(unsigned off) {
    float2 r;
    asm volatile("ld.shared.v2.f32 {%0,%1}, [%2];" : "=f"(r.x), "=f"(r.y) : "r"(off));
    return r;
}
__device__ __forceinline__ float lds_f(unsigned off) {
    float r; asm volatile("ld.shared.f32 %0, [%1];" : "=f"(r) : "r"(off)); return r;
}
__device__ __forceinline__ void fma2(u64 &d, u64 a, u64 b) {
    asm("fma.rn.f32x2 %0, %1, %2, %0;" : "+l"(d) : "l"(a), "l"(b));
}
__device__ __forceinline__ u64 dup2(float v) {
    u64 d; asm("mov.b64 %0, {%1,%1};" : "=l"(d) : "f"(v)); return d;
}
__device__ __forceinline__ float2 unpack2(u64 v) {
    float2 r; asm("mov.b64 {%0,%1}, %2;" : "=f"(r.x), "=f"(r.y) : "l"(v)); return r;
}

__global__ void lde_dummy() {}

__global__ __launch_bounds__(256, 2) void lde_phase1(
    const float* __restrict__ x,
    const float* __restrict__ s,
    const float* __restrict__ m)
{
    extern __shared__ float smf[];
    float* x_s = smf;                         // 128*130 f (66560 B)
    float* m_s = x_s + TILE_T * XS_LD;        // union: m[i][k] dense (8192 f)
    float* w_s = m_s;                         //        w[r][k] WS_LD  (8704 f)
    float* xn  = m_s + TILE_T * WS_LD;        // 128
    float* mn  = xn + TILE_T;                 // 64
    float* s_s = mn + NOUT;                   // 64

    const int tid = threadIdx.x;
    const int c   = blockIdx.x;
    const int b   = blockIdx.y;
    const float* xg = x + ((size_t)b * T_ + (size_t)c * TILE_T) * NIN;

    // ---- load M natural [i][k]: dense float4 copy ----
    for (int e = tid; e < (NIN * NOUT) / 4; e += 256) {
        float4 v = reinterpret_cast<const float4*>(m)[e];
        reinterpret_cast<float4*>(m_s)[e] = v;
    }
    // ---- load X tile ----
    for (int e = tid; e < TILE_T * (NIN / 4); e += 256) {
        int r = e >> 5, i4 = (e & 31) * 4;
        float4 v = reinterpret_cast<const float4*>(xg + r * NIN)[e & 31];
        float* dst = x_s + r * XS_LD + i4;
        *reinterpret_cast<float2*>(dst)     = make_float2(v.x, v.y);
        *reinterpret_cast<float2*>(dst + 2) = make_float2(v.z, v.w);
    }
    __syncthreads();

    const unsigned xb = (unsigned)__cvta_generic_to_shared(x_s);
    const unsigned mb = (unsigned)__cvta_generic_to_shared(m_s);
    const unsigned wb = (unsigned)__cvta_generic_to_shared(w_s);

    // ---- norms in parallel: tids 0-127 xn, 128-191 mn, 192-255 s_s ----
    if (tid < TILE_T) {
        const unsigned base = xb + (unsigned)(tid * XS_LD) * 4u;
        float a = 0.f;
        #pragma unroll 8
        for (int i = 0; i < NIN; i += 2) {
            float2 v = lds_v2f(base + (unsigned)i * 4u);
            a += v.x * v.x + v.y * v.y;
        }
        xn[tid] = a;
    } else if (tid < 192) {
        const int k = tid - 128;
        float a = 0.f;
        #pragma unroll 8
        for (int i = 0; i < NIN; i++) {
            float v = lds_f(mb + (unsigned)(i * NOUT + k) * 4u);
            a += v * v;
        }
        mn[k] = a;
    } else {
        s_s[tid - 192] = s[tid - 192];
    }
    __syncthreads();

    // ======== GEMM1: dot[r][k], tile 8r x 4k per thread ========
    const int kb = tid & 15;          // k = 4*kb .. 4*kb+3
    const int rb = tid >> 4;          // 0..15
    const int r0 = rb * 8;
    const int k0 = kb * 4;
    u64 acc[8][2];                    // [u=row][j=kpair]
    #pragma unroll
    for (int u = 0; u < 8; u++) { acc[u][0] = 0ull; acc[u][1] = 0ull; }

    const unsigned ax = xb + (unsigned)(r0 * XS_LD) * 4u;
    const unsigned bx = mb + (unsigned)k0 * 4u;

    #pragma unroll 2
    for (int i = 0; i < NIN; i += 2) {
        float2 av[8];
        #pragma unroll
        for (int u = 0; u < 8; u++)
            av[u] = lds_v2f(ax + (unsigned)(u * XS_LD + i) * 4u);
        u64 bp0, bp1, cp0, cp1;
        lds_v2u(bp0, bp1, bx + (unsigned)(i * NOUT) * 4u);
        lds_v2u(cp0, cp1, bx + (unsigned)((i + 1) * NOUT) * 4u);
        #pragma unroll
        for (int u = 0; u < 8; u++) {
            u64 a0 = dup2(av[u].x), a1 = dup2(av[u].y);
            fma2(acc[u][0], a0, bp0);
            fma2(acc[u][1], a0, bp1);
            fma2(acc[u][0], a1, cp0);
            fma2(acc[u][1], a1, cp1);
        }
    }

    // All GEMM1 reads of m_s must complete before w_s (alias) is written.
    __syncthreads();

    // ======== d-transform + softmax over k (16-lane xor shuffles) ========
    float mnl[4], ssl[4];
    #pragma unroll
    for (int q = 0; q < 4; q++) { mnl[q] = mn[k0 + q]; ssl[q] = s_s[k0 + q]; }

    #pragma unroll
    for (int u = 0; u < 8; u++) {
        const int r = r0 + u;
        const float xr = xn[r];
        float dv[4];
        float2 p0 = unpack2(acc[u][0]);
        float2 p1 = unpack2(acc[u][1]);
        dv[0] = ssl[0] * (xr - 2.f * p0.x + mnl[0]);
        dv[1] = ssl[1] * (xr - 2.f * p0.y + mnl[1]);
        dv[2] = ssl[2] * (xr - 2.f * p1.x + mnl[2]);
        dv[3] = ssl[3] * (xr - 2.f * p1.y + mnl[3]);

        float mx = fmaxf(fmaxf(dv[0], dv[1]), fmaxf(dv[2], dv[3]));
        #pragma unroll
        for (int off = 1; off < 16; off <<= 1)
            mx = fmaxf(mx, __shfl_xor_sync(0xffffffffu, mx, off));

        float ev[4], sum = 0.f;
        #pragma unroll
        for (int q = 0; q < 4; q++) { ev[q] = __expf(dv[q] - mx); sum += ev[q]; }
        #pragma unroll
        for (int off = 1; off < 16; off <<= 1)
            sum += __shfl_xor_sync(0xffffffffu, sum, off);

        const float inv = 1.f / sum;
        *reinterpret_cast<float4*>(w_s + r * WS_LD + k0) =
            make_float4(ev[0]*inv, ev[1]*inv, ev[2]*inv, ev[3]*inv);
    }
    __syncthreads();

    // ======== GEMM2: E[i][k] = sum_r w[r][k]*x[r][i], tile 4k x 8i ========
    const int ib = tid >> 4;          // i = ib*8 .. ib*8+7
    const int i0 = ib * 8;
    u64 acc2[2][8];                   // [j=kpair][v=i]
    #pragma unroll
    for (int v = 0; v < 8; v++) { acc2[0][v] = 0ull; acc2[1][v] = 0ull; }

    const unsigned wx = wb + (unsigned)k0 * 4u;
    const unsigned xi = xb + (unsigned)i0 * 4u;

    #pragma unroll 4
    for (int r = 0; r < TILE_T; r++) {
        u64 wp0, wp1;
        lds_v2u(wp0, wp1, wx + (unsigned)(r * WS_LD) * 4u);
        float2 xv[4];
        #pragma unroll
        for (int j = 0; j < 4; j++)
            xv[j] = lds_v2f(xi + (unsigned)(r * XS_LD + 2 * j) * 4u);
        #pragma unroll
        for (int j2 = 0; j2 < 4; j2++) {
            u64 xd0 = dup2(xv[j2].x), xd1 = dup2(xv[j2].y);
            fma2(acc2[0][2*j2],   wp0, xd0);
            fma2(acc2[1][2*j2],   wp1, xd0);
            fma2(acc2[0][2*j2+1], wp0, xd1);
            fma2(acc2[1][2*j2+1], wp1, xd1);
        }
    }

    float* pe = g_partE + (size_t)(b * CHUNKS + c) * NIN * NOUT;
    #pragma unroll
    for (int v = 0; v < 8; v++) {
        ulonglong2 o; o.x = acc2[0][v]; o.y = acc2[1][v];
        *reinterpret_cast<ulonglong2*>(pe + (i0 + v) * NOUT + k0) = o;
    }

    // ---- per-chunk wsum[k] ----
    if (tid < NOUT) {
        float a = 0.f;
        #pragma unroll 8
        for (int r = 0; r < TILE_T; r++) a += w_s[r * WS_LD + tid];
        g_partWS[(b * CHUNKS + c) * NOUT + tid] = a;
    }
}

__global__ __launch_bounds__(256) void lde_phase2(
    const float* __restrict__ m, float* __restrict__ out)
{
    const int g  = blockIdx.x * 256 + threadIdx.x;  // 65536 = B*NIN*32
    const int b  = g >> 12;
    const int i  = (g >> 5) & 127;
    const int k2 = g & 31;                          // pair of k

    float2 se = make_float2(0.f, 0.f);
    float2 sw = make_float2(0.f, 0.f);
    #pragma unroll
    for (int c = 0; c < CHUNKS; c++) {
        const float2 v = *reinterpret_cast<const float2*>(
            g_partE + ((size_t)((b * CHUNKS + c) * NIN + i)) * NOUT + k2 * 2);
        se.x += v.x; se.y += v.y;
        const float2 wv = *reinterpret_cast<const float2*>(
            g_partWS + (b * CHUNKS + c) * NOUT + k2 * 2);
        sw.x += wv.x; sw.y += wv.y;
    }
    const float2 mv = *reinterpret_cast<const float2*>(m + i * NOUT + k2 * 2);
    const float inv_t = 1.f / (float)T_;
    float* ob = out + (size_t)b * NOUT * NIN + i;
    ob[(k2 * 2 + 0) * NIN] = (se.x - mv.x * sw.x) * inv_t;
    ob[(k2 * 2 + 1) * NIN] = (se.y - mv.y * sw.y) * inv_t;
}

extern "C" void kernel_launch(void* const* d_in, const int* in_sizes, int n_in,
                              void* d_out, int out_size)
{
    const float* x = nullptr; const float* s = nullptr; const float* m = nullptr;
    for (int i = 0; i < n_in; i++) {
        if      (in_sizes[i] == B_ * T_ * NIN) x = (const float*)d_in[i];
        else if (in_sizes[i] == NOUT)          s = (const float*)d_in[i];
        else if (in_sizes[i] == NIN * NOUT)    m = (const float*)d_in[i];
    }
    float* out = (float*)d_out;

    const int smem_bytes =
        (TILE_T * XS_LD + TILE_T * WS_LD + TILE_T + 2 * NOUT)
        * (int)sizeof(float);   // ~102 KB

    cudaFuncSetAttribute(lde_phase1,
                         cudaFuncAttributeMaxDynamicSharedMemorySize, smem_bytes);

    // 3 launches/call: with the +2 stream offset, ncu -s 5 captures phase1.
    lde_phase1<<<dim3(CHUNKS, B_), 256, smem_bytes>>>(x, s, m);
    lde_phase2<<<(B_ * NIN * 32) / 256, 256>>>(m, out);
    lde_dummy<<<1, 32>>>();
}

// round 10
// speedup vs baseline: 2.1869x; 1.0069x over previous
#include <cuda_runtime.h>

// LDE_58961311040249 — R9: 256 thin threads (8rx4k / 4kx8i tiles), 2 CTAs/SM,
// 16 warps/SM to cover LDS latency (R8 profile: issue 30.8%, no pipe saturated).
//   d[b,t,k]  = s[k] * (||x_bt||^2 - 2 x_bt·m_k + ||m_k||^2)
//   w         = softmax_k(d)
//   out[b,k,i]= (sum_t w*x_i)/T - m[i,k]*(sum_t w)/T

#define B_      16
#define T_      2048
#define NIN     128
#define NOUT    64
#define CHUNKS  16
#define TILE_T  (T_ / CHUNKS)   // 128

#define XS_LD   130   // x row stride (floats)
#define WS_LD   68    // w row stride (floats)

__device__ float g_partE [B_ * CHUNKS * NIN * NOUT];  // [b][c][i][k], 8 MB
__device__ float g_partWS[B_ * CHUNKS * NOUT];

typedef unsigned long long u64;

__device__ __forceinline__ void lds_v2u(u64 &p0, u64 &p1, unsigned off) {
    asm volatile("ld.shared.v2.u64 {%0,%1}, [%2];" : "=l"(p0), "=l"(p1) : "r"(off));
}
__device__ __forceinline__ float2 lds_v2f(unsigned off) {
    float2 r;
    asm volatile("ld.shared.v2.f32 {%0,%1}, [%2];" : "=f"(r.x), "=f"(r.y) : "r"(off));
    return r;
}
__device__ __forceinline__ float lds_f(unsigned off) {
    float r; asm volatile("ld.shared.f32 %0, [%1];" : "=f"(r) : "r"(off)); return r;
}
__device__ __forceinline__ void fma2(u64 &d, u64 a, u64 b) {
    asm("fma.rn.f32x2 %0, %1, %2, %0;" : "+l"(d) : "l"(a), "l"(b));
}
__device__ __forceinline__ u64 dup2(float v) {
    u64 d; asm("mov.b64 %0, {%1,%1};" : "=l"(d) : "f"(v)); return d;
}
__device__ __forceinline__ float2 unpack2(u64 v) {
    float2 r; asm("mov.b64 {%0,%1}, %2;" : "=f"(r.x), "=f"(r.y) : "l"(v)); return r;
}

__global__ void lde_dummy() {}

__global__ __launch_bounds__(256, 2) void lde_phase1(
    const float* __restrict__ x,
    const float* __restrict__ s,
    const float* __restrict__ m)
{
    extern __shared__ float smf[];
    float* x_s = smf;                         // 128*130 f (66560 B)
    float* m_s = x_s + TILE_T * XS_LD;        // union: m[i][k] dense (8192 f)
    float* w_s = m_s;                         //        w[r][k] WS_LD  (8704 f)
    float* xn  = m_s + TILE_T * WS_LD;        // 128
    float* mn  = xn + TILE_T;                 // 64
    float* s_s = mn + NOUT;                   // 64

    const int tid = threadIdx.x;
    const int c   = blockIdx.x;
    const int b   = blockIdx.y;
    const float* xg = x + ((size_t)b * T_ + (size_t)c * TILE_T) * NIN;

    // ---- load M natural [i][k]: dense float4 copy ----
    for (int e = tid; e < (NIN * NOUT) / 4; e += 256) {
        float4 v = reinterpret_cast<const float4*>(m)[e];
        reinterpret_cast<float4*>(m_s)[e] = v;
    }
    // ---- load X tile ----
    for (int e = tid; e < TILE_T * (NIN / 4); e += 256) {
        int r = e >> 5, i4 = (e & 31) * 4;
        float4 v = reinterpret_cast<const float4*>(xg + r * NIN)[e & 31];
        float* dst = x_s + r * XS_LD + i4;
        *reinterpret_cast<float2*>(dst)     = make_float2(v.x, v.y);
        *reinterpret_cast<float2*>(dst + 2) = make_float2(v.z, v.w);
    }
    __syncthreads();

    const unsigned xb = (unsigned)__cvta_generic_to_shared(x_s);
    const unsigned mb = (unsigned)__cvta_generic_to_shared(m_s);
    const unsigned wb = (unsigned)__cvta_generic_to_shared(w_s);

    // ---- norms in parallel: tids 0-127 xn, 128-191 mn, 192-255 s_s ----
    if (tid < TILE_T) {
        const unsigned base = xb + (unsigned)(tid * XS_LD) * 4u;
        float a = 0.f;
        #pragma unroll 8
        for (int i = 0; i < NIN; i += 2) {
            float2 v = lds_v2f(base + (unsigned)i * 4u);
            a += v.x * v.x + v.y * v.y;
        }
        xn[tid] = a;
    } else if (tid < 192) {
        const int k = tid - 128;
        float a = 0.f;
        #pragma unroll 8
        for (int i = 0; i < NIN; i++) {
            float v = lds_f(mb + (unsigned)(i * NOUT + k) * 4u);
            a += v * v;
        }
        mn[k] = a;
    } else {
        s_s[tid - 192] = s[tid - 192];
    }
    __syncthreads();

    // ======== GEMM1: dot[r][k], tile 8r x 4k per thread ========
    const int kb = tid & 15;          // k = 4*kb .. 4*kb+3
    const int rb = tid >> 4;          // 0..15
    const int r0 = rb * 8;
    const int k0 = kb * 4;
    u64 acc[8][2];                    // [u=row][j=kpair]
    #pragma unroll
    for (int u = 0; u < 8; u++) { acc[u][0] = 0ull; acc[u][1] = 0ull; }

    const unsigned ax = xb + (unsigned)(r0 * XS_LD) * 4u;
    const unsigned bx = mb + (unsigned)k0 * 4u;

    #pragma unroll 2
    for (int i = 0; i < NIN; i += 2) {
        float2 av[8];
        #pragma unroll
        for (int u = 0; u < 8; u++)
            av[u] = lds_v2f(ax + (unsigned)(u * XS_LD + i) * 4u);
        u64 bp0, bp1, cp0, cp1;
        lds_v2u(bp0, bp1, bx + (unsigned)(i * NOUT) * 4u);
        lds_v2u(cp0, cp1, bx + (unsigned)((i + 1) * NOUT) * 4u);
        #pragma unroll
        for (int u = 0; u < 8; u++) {
            u64 a0 = dup2(av[u].x), a1 = dup2(av[u].y);
            fma2(acc[u][0], a0, bp0);
            fma2(acc[u][1], a0, bp1);
            fma2(acc[u][0], a1, cp0);
            fma2(acc[u][1], a1, cp1);
        }
    }

    // All GEMM1 reads of m_s must complete before w_s (alias) is written.
    __syncthreads();

    // ======== d-transform + softmax over k (16-lane xor shuffles) ========
    float mnl[4], ssl[4];
    #pragma unroll
    for (int q = 0; q < 4; q++) { mnl[q] = mn[k0 + q]; ssl[q] = s_s[k0 + q]; }

    #pragma unroll
    for (int u = 0; u < 8; u++) {
        const int r = r0 + u;
        const float xr = xn[r];
        float dv[4];
        float2 p0 = unpack2(acc[u][0]);
        float2 p1 = unpack2(acc[u][1]);
        dv[0] = ssl[0] * (xr - 2.f * p0.x + mnl[0]);
        dv[1] = ssl[1] * (xr - 2.f * p0.y + mnl[1]);
        dv[2] = ssl[2] * (xr - 2.f * p1.x + mnl[2]);
        dv[3] = ssl[3] * (xr - 2.f * p1.y + mnl[3]);

        float mx = fmaxf(fmaxf(dv[0], dv[1]), fmaxf(dv[2], dv[3]));
        #pragma unroll
        for (int off = 1; off < 16; off <<= 1)
            mx = fmaxf(mx, __shfl_xor_sync(0xffffffffu, mx, off));

        float ev[4], sum = 0.f;
        #pragma unroll
        for (int q = 0; q < 4; q++) { ev[q] = __expf(dv[q] - mx); sum += ev[q]; }
        #pragma unroll
        for (int off = 1; off < 16; off <<= 1)
            sum += __shfl_xor_sync(0xffffffffu, sum, off);

        const float inv = 1.f / sum;
        *reinterpret_cast<float4*>(w_s + r * WS_LD + k0) =
            make_float4(ev[0]*inv, ev[1]*inv, ev[2]*inv, ev[3]*inv);
    }
    __syncthreads();

    // ======== GEMM2: E[i][k] = sum_r w[r][k]*x[r][i], tile 4k x 8i ========
    const int ib = tid >> 4;          // i = ib*8 .. ib*8+7
    const int i0 = ib * 8;
    u64 acc2[2][8];                   // [j=kpair][v=i]
    #pragma unroll
    for (int v = 0; v < 8; v++) { acc2[0][v] = 0ull; acc2[1][v] = 0ull; }

    const unsigned wx = wb + (unsigned)k0 * 4u;
    const unsigned xi = xb + (unsigned)i0 * 4u;

    #pragma unroll 4
    for (int r = 0; r < TILE_T; r++) {
        u64 wp0, wp1;
        lds_v2u(wp0, wp1, wx + (unsigned)(r * WS_LD) * 4u);
        float2 xv[4];
        #pragma unroll
        for (int j = 0; j < 4; j++)
            xv[j] = lds_v2f(xi + (unsigned)(r * XS_LD + 2 * j) * 4u);
        #pragma unroll
        for (int j2 = 0; j2 < 4; j2++) {
            u64 xd0 = dup2(xv[j2].x), xd1 = dup2(xv[j2].y);
            fma2(acc2[0][2*j2],   wp0, xd0);
            fma2(acc2[1][2*j2],   wp1, xd0);
            fma2(acc2[0][2*j2+1], wp0, xd1);
            fma2(acc2[1][2*j2+1], wp1, xd1);
        }
    }

    float* pe = g_partE + (size_t)(b * CHUNKS + c) * NIN * NOUT;
    #pragma unroll
    for (int v = 0; v < 8; v++) {
        ulonglong2 o; o.x = acc2[0][v]; o.y = acc2[1][v];
        *reinterpret_cast<ulonglong2*>(pe + (i0 + v) * NOUT + k0) = o;
    }

    // ---- per-chunk wsum[k] ----
    if (tid < NOUT) {
        float a = 0.f;
        #pragma unroll 8
        for (int r = 0; r < TILE_T; r++) a += w_s[r * WS_LD + tid];
        g_partWS[(b * CHUNKS + c) * NOUT + tid] = a;
    }
}

__global__ __launch_bounds__(256) void lde_phase2(
    const float* __restrict__ m, float* __restrict__ out)
{
    const int g  = blockIdx.x * 256 + threadIdx.x;  // 65536 = B*NIN*32
    const int b  = g >> 12;
    const int i  = (g >> 5) & 127;
    const int k2 = g & 31;                          // pair of k

    float2 se = make_float2(0.f, 0.f);
    float2 sw = make_float2(0.f, 0.f);
    #pragma unroll
    for (int c = 0; c < CHUNKS; c++) {
        const float2 v = *reinterpret_cast<const float2*>(
            g_partE + ((size_t)((b * CHUNKS + c) * NIN + i)) * NOUT + k2 * 2);
        se.x += v.x; se.y += v.y;
        const float2 wv = *reinterpret_cast<const float2*>(
            g_partWS + (b * CHUNKS + c) * NOUT + k2 * 2);
        sw.x += wv.x; sw.y += wv.y;
    }
    const float2 mv = *reinterpret_cast<const float2*>(m + i * NOUT + k2 * 2);
    const float inv_t = 1.f / (float)T_;
    float* ob = out + (size_t)b * NOUT * NIN + i;
    ob[(k2 * 2 + 0) * NIN] = (se.x - mv.x * sw.x) * inv_t;
    ob[(k2 * 2 + 1) * NIN] = (se.y - mv.y * sw.y) * inv_t;
}

extern "C" void kernel_launch(void* const* d_in, const int* in_sizes, int n_in,
                              void* d_out, int out_size)
{
    const float* x = nullptr; const float* s = nullptr; const float* m = nullptr;
    for (int i = 0; i < n_in; i++) {
        if      (in_sizes[i] == B_ * T_ * NIN) x = (const float*)d_in[i];
        else if (in_sizes[i] == NOUT)          s = (const float*)d_in[i];
        else if (in_sizes[i] == NIN * NOUT)    m = (const float*)d_in[i];
    }
    float* out = (float*)d_out;

    const int smem_bytes =
        (TILE_T * XS_LD + TILE_T * WS_LD + TILE_T + 2 * NOUT)
        * (int)sizeof(float);   // ~102 KB

    cudaFuncSetAttribute(lde_phase1,
                         cudaFuncAttributeMaxDynamicSharedMemorySize, smem_bytes);

    // 3 launches/call: with the +2 stream offset, ncu -s 5 captures phase1.
    lde_phase1<<<dim3(CHUNKS, B_), 256, smem_bytes>>>(x, s, m);
    lde_phase2<<<(B_ * NIN * 32) / 256, 256>>>(m, out);
    lde_dummy<<<1, 32>>>();
}